// round 1
// baseline (speedup 1.0000x reference)
#include <cuda_runtime.h>
#include <math.h>

// Problem dims (static)
#define NB   32
#define NS   4096
#define ND   64
#define NL   13
#define NWR  13
#define NHF  128
#define NHV  128
#define NCLS 2
#define ROWS (NB*NS)          // 131072 rows of (S*B) flattened
#define SD   (NS*ND)          // 262144

// Scratch (device globals; no allocation inside kernel_launch)
__device__ float g_X[(size_t)ROWS*ND];            // 32 MB embedded input
__device__ float g_F[(size_t)NWR*ROWS*NL];        // ~84.5 MB FNet outputs
__device__ float g_V[(size_t)ROWS*ND];            // 32 MB VNet output
__device__ float g_Z0[(size_t)ROWS*ND];           // ping
__device__ float g_Z1[(size_t)ROWS*ND];           // pong

__constant__ int c_off[NL] = {0,1,2,4,8,16,32,64,128,256,512,1024,2048};

__device__ __forceinline__ float gelu_exact(float x) {
    return 0.5f * x * (1.0f + erff(x * 0.7071067811865476f));
}

// ---------------------------------------------------------------------------
// Embedding gather: X[b,s,:] = emb[tok[b,s], :]   (float4 over D)
// ---------------------------------------------------------------------------
__global__ void embed_kernel(const int* __restrict__ tok,
                             const float* __restrict__ emb) {
    int idx = blockIdx.x * blockDim.x + threadIdx.x;   // over ROWS*16
    int row = idx >> 4;
    int c   = idx & 15;
    int t   = tok[row];
    reinterpret_cast<float4*>(g_X)[idx] =
        reinterpret_cast<const float4*>(emb)[t * 16 + c];
}

// ---------------------------------------------------------------------------
// FNet (all 13 stacked nets): F[k,row,:] = gelu(X@fW1[k]+fb1[k]) @ fW2[k] + fb2[k]
// Block: 128 threads, 64 rows, one k. Weight col of fW1 in registers.
// Dynamic smem: Xs(64x64) | Hs(64x128) | W2s(128x13)
// ---------------------------------------------------------------------------
__global__ __launch_bounds__(128) void fnet_kernel(
    const float* __restrict__ fW1, const float* __restrict__ fb1,
    const float* __restrict__ fW2, const float* __restrict__ fb2) {
    extern __shared__ float smem[];
    float* Xs  = smem;                  // 4096 floats
    float* Hs  = smem + 64*64;          // 8192 floats
    float* W2s = Hs + 64*128;           // 1664 floats

    const int k    = blockIdx.y;
    const int row0 = blockIdx.x * 64;
    const int t    = threadIdx.x;

    // load X tile (coalesced float4)
    const float4* Xv  = reinterpret_cast<const float4*>(g_X + (size_t)row0 * ND);
    float4*       Xsv = reinterpret_cast<float4*>(Xs);
#pragma unroll
    for (int i = 0; i < 8; i++) Xsv[t + 128*i] = Xv[t + 128*i];
    // load fW2[k] tile
    for (int i = t; i < NHF*NL; i += 128) W2s[i] = fW2[(size_t)k*NHF*NL + i];

    // fW1 column for this thread's hidden unit
    float w[64];
#pragma unroll
    for (int d = 0; d < 64; d++) w[d] = fW1[((size_t)k*ND + d)*NHF + t];
    const float b1 = fb1[k*NHF + t];
    __syncthreads();

#pragma unroll 4
    for (int r = 0; r < 64; r++) {
        const float4* xr = reinterpret_cast<const float4*>(Xs + r*64);
        float acc = b1;
#pragma unroll
        for (int d4 = 0; d4 < 16; d4++) {
            float4 xv = xr[d4];
            acc = fmaf(w[4*d4+0], xv.x, acc);
            acc = fmaf(w[4*d4+1], xv.y, acc);
            acc = fmaf(w[4*d4+2], xv.z, acc);
            acc = fmaf(w[4*d4+3], xv.w, acc);
        }
        Hs[r*128 + t] = gelu_exact(acc);
    }
    __syncthreads();

    // stage 2: 64*13 = 832 outputs
    float* Fout = g_F + ((size_t)k*ROWS + row0) * NL;
    const float* fb2k = fb2 + k*NL;
    for (int o = t; o < 64*NL; o += 128) {
        int r = o / NL;
        int l = o - r*NL;
        float acc = fb2k[l];
        const float4* hr = reinterpret_cast<const float4*>(Hs + r*128);
#pragma unroll
        for (int h4 = 0; h4 < 32; h4++) {
            float4 hv = hr[h4];
            acc = fmaf(hv.x, W2s[(4*h4+0)*NL + l], acc);
            acc = fmaf(hv.y, W2s[(4*h4+1)*NL + l], acc);
            acc = fmaf(hv.z, W2s[(4*h4+2)*NL + l], acc);
            acc = fmaf(hv.w, W2s[(4*h4+3)*NL + l], acc);
        }
        Fout[o] = acc;
    }
}

// ---------------------------------------------------------------------------
// VNet: V = gelu(X@vW1+vb1) @ vW2 + vb2
// Block: 128 threads, 64 rows. Dyn smem: Xs(64x64) | Hs(64x128) | W2s(128x64)
// ---------------------------------------------------------------------------
__global__ __launch_bounds__(128) void vnet_kernel(
    const float* __restrict__ vW1, const float* __restrict__ vb1,
    const float* __restrict__ vW2, const float* __restrict__ vb2) {
    extern __shared__ float smem[];
    float* Xs  = smem;                  // 4096
    float* Hs  = smem + 64*64;          // 8192
    float* W2s = Hs + 64*128;           // 8192

    const int row0 = blockIdx.x * 64;
    const int t    = threadIdx.x;

    const float4* Xv  = reinterpret_cast<const float4*>(g_X + (size_t)row0 * ND);
    float4*       Xsv = reinterpret_cast<float4*>(Xs);
#pragma unroll
    for (int i = 0; i < 8; i++) Xsv[t + 128*i] = Xv[t + 128*i];
    float4*       W2sv = reinterpret_cast<float4*>(W2s);
    const float4* w2v  = reinterpret_cast<const float4*>(vW2);
#pragma unroll
    for (int i = 0; i < 16; i++) W2sv[t + 128*i] = w2v[t + 128*i];

    float w[64];
#pragma unroll
    for (int d = 0; d < 64; d++) w[d] = vW1[(size_t)d*NHV + t];
    const float b1 = vb1[t];
    __syncthreads();

#pragma unroll 4
    for (int r = 0; r < 64; r++) {
        const float4* xr = reinterpret_cast<const float4*>(Xs + r*64);
        float acc = b1;
#pragma unroll
        for (int d4 = 0; d4 < 16; d4++) {
            float4 xv = xr[d4];
            acc = fmaf(w[4*d4+0], xv.x, acc);
            acc = fmaf(w[4*d4+1], xv.y, acc);
            acc = fmaf(w[4*d4+2], xv.z, acc);
            acc = fmaf(w[4*d4+3], xv.w, acc);
        }
        Hs[r*128 + t] = gelu_exact(acc);
    }
    __syncthreads();

    // stage 2: each thread owns fixed output column d, 32 rows
    const int d     = t & 63;
    const int rbase = t >> 6;   // 0 or 1
    float acc2[32];
#pragma unroll
    for (int r = 0; r < 32; r++) acc2[r] = 0.f;
#pragma unroll 4
    for (int h4 = 0; h4 < 32; h4++) {
        const float w0 = W2s[(4*h4+0)*64 + d];
        const float w1 = W2s[(4*h4+1)*64 + d];
        const float w2 = W2s[(4*h4+2)*64 + d];
        const float w3 = W2s[(4*h4+3)*64 + d];
#pragma unroll
        for (int r = 0; r < 32; r++) {
            const float4 hv = *reinterpret_cast<const float4*>(Hs + (rbase + 2*r)*128 + 4*h4);
            acc2[r] = fmaf(hv.x, w0, acc2[r]);
            acc2[r] = fmaf(hv.y, w1, acc2[r]);
            acc2[r] = fmaf(hv.z, w2, acc2[r]);
            acc2[r] = fmaf(hv.w, w3, acc2[r]);
        }
    }
    const float bb = vb2[d];
#pragma unroll
    for (int r = 0; r < 32; r++)
        g_V[((size_t)row0 + rbase + 2*r)*ND + d] = acc2[r] + bb;
}

// ---------------------------------------------------------------------------
// One chord round: Zout[b,i,:] = sum_l Fk[b,i,l] * Zin[b,(i+off_l)&4095,:] + V
// float4 over D. Thread = (row, 16-byte chunk).
// ---------------------------------------------------------------------------
__global__ __launch_bounds__(256) void chord_kernel(
    const float* __restrict__ Fk, const float* __restrict__ Zin,
    const float* __restrict__ V, float* __restrict__ Zout) {
    int idx = blockIdx.x * blockDim.x + threadIdx.x;  // over ROWS*16
    int c   = idx & 15;
    int row = idx >> 4;          // b*S + i
    int b   = row >> 12;
    int i   = row & (NS - 1);

    const float4* Zb = reinterpret_cast<const float4*>(Zin) + ((size_t)b << 12) * 16;
    const float*  f  = Fk + (size_t)row * NL;

    float4 acc = make_float4(0.f, 0.f, 0.f, 0.f);
#pragma unroll
    for (int l = 0; l < NL; l++) {
        float  fv = f[l];
        int    j  = (i + c_off[l]) & (NS - 1);
        float4 z  = Zb[j * 16 + c];
        acc.x = fmaf(fv, z.x, acc.x);
        acc.y = fmaf(fv, z.y, acc.y);
        acc.z = fmaf(fv, z.z, acc.z);
        acc.w = fmaf(fv, z.w, acc.w);
    }
    float4 v = reinterpret_cast<const float4*>(V)[idx];
    acc.x += v.x; acc.y += v.y; acc.z += v.z; acc.w += v.w;
    reinterpret_cast<float4*>(Zout)[idx] = acc;
}

// ---------------------------------------------------------------------------
// Logits: out[b,c] = dot(V[b,:,:].flat, finW[c,:]) + finb[c]
// One block per (b,c), 512 threads, float4 grid-stride + block reduce.
// ---------------------------------------------------------------------------
__global__ __launch_bounds__(512) void logits_kernel(
    const float* __restrict__ finW, const float* __restrict__ finb,
    float* __restrict__ out) {
    const int b = blockIdx.x >> 1;
    const int c = blockIdx.x & 1;
    const int t = threadIdx.x;

    const float4* v = reinterpret_cast<const float4*>(g_V + (size_t)b * SD);
    const float4* w = reinterpret_cast<const float4*>(finW + (size_t)c * SD);
    float acc = 0.f;
    for (int i = t; i < SD/4; i += 512) {
        float4 vv = v[i], ww = w[i];
        acc = fmaf(vv.x, ww.x, acc);
        acc = fmaf(vv.y, ww.y, acc);
        acc = fmaf(vv.z, ww.z, acc);
        acc = fmaf(vv.w, ww.w, acc);
    }
    __shared__ float red[512];
    red[t] = acc;
    __syncthreads();
#pragma unroll
    for (int s = 256; s > 0; s >>= 1) {
        if (t < s) red[t] += red[t + s];
        __syncthreads();
    }
    if (t == 0) out[b * NCLS + c] = red[0] + finb[c];
}

// ---------------------------------------------------------------------------
extern "C" void kernel_launch(void* const* d_in, const int* in_sizes, int n_in,
                              void* d_out, int out_size) {
    const int*   tok  = (const int*)  d_in[0];
    const float* emb  = (const float*)d_in[1];
    const float* fW1  = (const float*)d_in[2];
    const float* fb1  = (const float*)d_in[3];
    const float* fW2  = (const float*)d_in[4];
    const float* fb2  = (const float*)d_in[5];
    const float* vW1  = (const float*)d_in[6];
    const float* vb1  = (const float*)d_in[7];
    const float* vW2  = (const float*)d_in[8];
    const float* vb2  = (const float*)d_in[9];
    const float* finW = (const float*)d_in[10];
    const float* finb = (const float*)d_in[11];
    float* out = (float*)d_out;

    // dynamic smem sizes
    const int fnet_smem = (64*64 + 64*128 + 128*NL) * 4;   // 55808 B
    const int vnet_smem = (64*64 + 64*128 + 128*64) * 4;   // 81920 B
    static bool attr_set = false;
    if (!attr_set) {
        cudaFuncSetAttribute(fnet_kernel, cudaFuncAttributeMaxDynamicSharedMemorySize, fnet_smem);
        cudaFuncSetAttribute(vnet_kernel, cudaFuncAttributeMaxDynamicSharedMemorySize, vnet_smem);
        attr_set = true;
    }

    embed_kernel<<<ROWS*16/256, 256>>>(tok, emb);

    dim3 fgrid(ROWS/64, NWR);
    fnet_kernel<<<fgrid, 128, fnet_smem>>>(fW1, fb1, fW2, fb2);
    vnet_kernel<<<ROWS/64, 128, vnet_smem>>>(vW1, vb1, vW2, vb2);

    // logits depend only on V
    logits_kernel<<<NB*NCLS, 512>>>(finW, finb, out);

    // chord rounds (ping-pong), last round writes Z straight into d_out
    float *pV, *pZ0, *pZ1, *pF;
    cudaGetSymbolAddress((void**)&pV,  g_V);
    cudaGetSymbolAddress((void**)&pZ0, g_Z0);
    cudaGetSymbolAddress((void**)&pZ1, g_Z1);
    cudaGetSymbolAddress((void**)&pF,  g_F);

    const bool bigOut = (out_size >= NB*NCLS + ROWS*ND);
    const float* zin = pV;
    for (int k = 0; k < NWR; k++) {
        float* zout;
        if (k == NWR - 1 && bigOut) zout = out + NB*NCLS;
        else                        zout = (k & 1) ? pZ1 : pZ0;
        chord_kernel<<<ROWS*16/256, 256>>>(pF + (size_t)k*ROWS*NL, zin, pV, zout);
        zin = zout;
    }
}